// round 2
// baseline (speedup 1.0000x reference)
#include <cuda_runtime.h>
#include <cuda_bf16.h>
#include <math_constants.h>

// KL(target || softmax(scores)), target = softmax(gaussian_pdf(classes; mu=label, std=1))
// kl_row = tlogt[L] - dot(T[L], s_row) + logsumexp(s_row);  out = mean over rows.

#define C 100

__device__ float  g_table[C * C];   // T[label][class]
__device__ float  g_ent[C];         // sum t*log t per label
__device__ double g_acc;            // global accumulator
__device__ int    g_is64;           // 1 if labels are int64, 0 if int32

// ---------------------------------------------------------------------------
// Kernel 0: detect label dtype (int64 little-endian => odd 32-bit words all 0)
// ---------------------------------------------------------------------------
__global__ void detect_labels(const int* __restrict__ labels_raw, int n) {
    // single thread
    int check = (n < 128) ? n : 128;
    int all_zero = 1;
    for (int i = 0; i < check; i++) {
        if (labels_raw[2 * i + 1] != 0) { all_zero = 0; break; }
    }
    g_is64 = all_zero;
    g_acc = 0.0;
}

// ---------------------------------------------------------------------------
// Kernel 1: build target table + entropy terms. 100 blocks x 32 threads.
// ---------------------------------------------------------------------------
__global__ void build_table() {
    const int L = blockIdx.x;
    const int lane = threadIdx.x;  // 0..31
    const float inv_norm = 0.39894228040143267794f;  // 1/sqrt(2*pi)

    float code[4];
    float esum = 0.f;
#pragma unroll
    for (int k = 0; k < 4; k++) {
        int c = lane + 32 * k;
        if (c < C) {
            float dd = (float)(c - L);
            code[k] = inv_norm * expf(-0.5f * dd * dd);
            esum += expf(code[k]);
        } else {
            code[k] = 0.f;
        }
    }
#pragma unroll
    for (int off = 16; off; off >>= 1)
        esum += __shfl_xor_sync(0xffffffffu, esum, off);

    float ls = logf(esum);
    float inv_s = 1.0f / esum;
    float tlt = 0.f;
#pragma unroll
    for (int k = 0; k < 4; k++) {
        int c = lane + 32 * k;
        if (c < C) {
            float t = expf(code[k]) * inv_s;
            g_table[L * C + c] = t;
            tlt += t * (code[k] - ls);  // t * log t
        }
    }
#pragma unroll
    for (int off = 16; off; off >>= 1)
        tlt += __shfl_xor_sync(0xffffffffu, tlt, off);

    if (lane == 0) g_ent[L] = tlt;
}

// ---------------------------------------------------------------------------
// Kernel 2: main streaming pass. One warp per row (row = 100 floats = 25 float4).
// ---------------------------------------------------------------------------
__global__ __launch_bounds__(256) void kl_main(const float* __restrict__ scores,
                                               const void* __restrict__ labels,
                                               int n) {
    const int warp_in_block = threadIdx.x >> 5;
    const int lane = threadIdx.x & 31;
    const int row = blockIdx.x * 8 + warp_in_block;

    __shared__ float s_partial;
    if (threadIdx.x == 0) s_partial = 0.f;
    __syncthreads();

    const bool valid = (row < n);

    float kl = 0.f;
    if (valid) {
        int L;
        if (lane == 0) {
            if (g_is64)
                L = (int)((const long long*)labels)[row];
            else
                L = ((const int*)labels)[row];
        }
        L = __shfl_sync(0xffffffffu, L, 0);

        const float4* srow = (const float4*)(scores + (size_t)row * C);
        const float4* trow = (const float4*)(g_table + L * C);

        float e = 0.f, d = 0.f;
        if (lane < 25) {
            float4 sv = srow[lane];
            float4 tv = trow[lane];
            e = __expf(sv.x) + __expf(sv.y) + __expf(sv.z) + __expf(sv.w);
            d = tv.x * sv.x + tv.y * sv.y + tv.z * sv.z + tv.w * sv.w;
        }
#pragma unroll
        for (int off = 16; off; off >>= 1) {
            e += __shfl_xor_sync(0xffffffffu, e, off);
            d += __shfl_xor_sync(0xffffffffu, d, off);
        }
        if (lane == 0)
            kl = g_ent[L] - d + __logf(e);
    }

    if (lane == 0 && valid)
        atomicAdd(&s_partial, kl);
    __syncthreads();
    if (threadIdx.x == 0)
        atomicAdd(&g_acc, (double)s_partial);
}

// ---------------------------------------------------------------------------
// Kernel 3: finalize
// ---------------------------------------------------------------------------
__global__ void finalize(float* __restrict__ out, int n) {
    out[0] = (float)(g_acc / (double)n);
}

extern "C" void kernel_launch(void* const* d_in, const int* in_sizes, int n_in,
                              void* d_out, int out_size) {
    const float* scores = (const float*)d_in[0];
    const void*  labels = d_in[1];
    const int n = in_sizes[1];  // number of rows / labels

    detect_labels<<<1, 1>>>((const int*)labels, n);
    build_table<<<C, 32>>>();
    int blocks = (n + 7) / 8;
    kl_main<<<blocks, 256>>>(scores, labels, n);
    finalize<<<1, 1>>>((float*)d_out, n);
}

// round 5
// speedup vs baseline: 1.4290x; 1.4290x over previous
#include <cuda_runtime.h>
#include <cuda_bf16.h>

// KL(target || softmax(scores)), target = softmax(gaussian_pdf(classes; mu=label, std=1))
// kl_row = tlogt[L] - dot(T[L], s_row) + logsumexp(s_row);  out = mean over rows.
//
// Launch structure (2 kernels):
//   prep:    build 100x100 target table + per-label entropy; detect label dtype
//            (int64 vs int32) with a 32-thread ballot; zero accumulators.
//   kl_main: streaming pass, 4 rows per warp with batched loads; hierarchical
//            reduce (warp -> shared -> fp64 REDG); last block writes output.

#define C 100
#define ROWS_PER_WARP 4
#define WARPS_PER_BLOCK 8
#define ROWS_PER_BLOCK (ROWS_PER_WARP * WARPS_PER_BLOCK)  // 32

__device__ float         g_table[C * C];   // T[label][class]
__device__ float         g_ent[C];         // sum t*log t per label
__device__ double        g_acc;            // global accumulator
__device__ unsigned int  g_count;          // finished-block counter
__device__ int           g_is64;           // 1 if labels are int64, 0 if int32

// ---------------------------------------------------------------------------
// Kernel 1: build target table + entropy terms; block 0 also detects label
// dtype and zeroes accumulators. Grid: C blocks x 32 threads.
// ---------------------------------------------------------------------------
__global__ void prep(const int* __restrict__ labels_raw, int n) {
    const int L = blockIdx.x;
    const int lane = threadIdx.x;  // 0..31
    const float inv_norm = 0.39894228040143267794f;  // 1/sqrt(2*pi)

    if (blockIdx.x == 0) {
        // int64 little-endian labels => odd 32-bit words are all zero.
        // Check first 128 words (labels < 100 so high word == 0 for int64).
        int nz = 0;
        int limit = (n < 128) ? n : 128;
#pragma unroll
        for (int k = 0; k < 4; k++) {
            int i = lane + 32 * k;
            if (i < limit && labels_raw[2 * i + 1] != 0) nz = 1;
        }
        unsigned int ballot = __ballot_sync(0xffffffffu, nz);
        if (lane == 0) {
            g_is64 = (ballot == 0u) ? 1 : 0;
            g_acc = 0.0;
            g_count = 0u;
        }
    }

    float code[4];
    float esum = 0.f;
#pragma unroll
    for (int k = 0; k < 4; k++) {
        int c = lane + 32 * k;
        if (c < C) {
            float dd = (float)(c - L);
            code[k] = inv_norm * expf(-0.5f * dd * dd);
            esum += expf(code[k]);
        } else {
            code[k] = 0.f;
        }
    }
#pragma unroll
    for (int off = 16; off; off >>= 1)
        esum += __shfl_xor_sync(0xffffffffu, esum, off);

    float ls = logf(esum);
    float inv_s = 1.0f / esum;
    float tlt = 0.f;
#pragma unroll
    for (int k = 0; k < 4; k++) {
        int c = lane + 32 * k;
        if (c < C) {
            float t = expf(code[k]) * inv_s;
            g_table[L * C + c] = t;
            tlt += t * (code[k] - ls);  // t * log t
        }
    }
#pragma unroll
    for (int off = 16; off; off >>= 1)
        tlt += __shfl_xor_sync(0xffffffffu, tlt, off);

    if (lane == 0) g_ent[L] = tlt;
}

// ---------------------------------------------------------------------------
// Kernel 2: main streaming pass + fused finalize.
// One warp handles 4 rows; all 8 float4 loads issued before dependent math.
// ---------------------------------------------------------------------------
__global__ __launch_bounds__(256) void kl_main(const float* __restrict__ scores,
                                               const void* __restrict__ labels,
                                               float* __restrict__ out,
                                               int n, int nblocks) {
    const int warp = threadIdx.x >> 5;
    const int lane = threadIdx.x & 31;
    const int base_row = (blockIdx.x * WARPS_PER_BLOCK + warp) * ROWS_PER_WARP;

    __shared__ float s_partial;
    if (threadIdx.x == 0) s_partial = 0.f;
    __syncthreads();

    // n is a multiple of ROWS_PER_BLOCK here (262144 % 32 == 0), but guard anyway.
    if (base_row < n) {
        // --- labels: lanes 0..3 each load one, then broadcast ---
        const int is64 = g_is64;
        int lab = 0;
        if (lane < ROWS_PER_WARP) {
            int r = base_row + lane;
            lab = is64 ? (int)((const long long*)labels)[r]
                       : ((const int*)labels)[r];
        }
        int L[ROWS_PER_WARP];
#pragma unroll
        for (int r = 0; r < ROWS_PER_WARP; r++)
            L[r] = __shfl_sync(0xffffffffu, lab, r);

        // --- batched loads: 8 independent float4 LDGs per lane ---
        float4 sv[ROWS_PER_WARP], tv[ROWS_PER_WARP];
        if (lane < 25) {
#pragma unroll
            for (int r = 0; r < ROWS_PER_WARP; r++)
                sv[r] = ((const float4*)(scores + (size_t)(base_row + r) * C))[lane];
#pragma unroll
            for (int r = 0; r < ROWS_PER_WARP; r++)
                tv[r] = ((const float4*)(g_table + L[r] * C))[lane];
        }

        // --- per-row exp-sum and dot ---
        float e[ROWS_PER_WARP], d[ROWS_PER_WARP];
#pragma unroll
        for (int r = 0; r < ROWS_PER_WARP; r++) {
            float ee = 0.f, dd = 0.f;
            if (lane < 25) {
                ee = __expf(sv[r].x) + __expf(sv[r].y) + __expf(sv[r].z) + __expf(sv[r].w);
                dd = tv[r].x * sv[r].x + tv[r].y * sv[r].y
                   + tv[r].z * sv[r].z + tv[r].w * sv[r].w;
            }
            e[r] = ee;
            d[r] = dd;
        }
#pragma unroll
        for (int off = 16; off; off >>= 1) {
#pragma unroll
            for (int r = 0; r < ROWS_PER_WARP; r++) {
                e[r] += __shfl_xor_sync(0xffffffffu, e[r], off);
                d[r] += __shfl_xor_sync(0xffffffffu, d[r], off);
            }
        }

        if (lane == 0) {
            float kl = 0.f;
#pragma unroll
            for (int r = 0; r < ROWS_PER_WARP; r++)
                kl += g_ent[L[r]] - d[r] + __logf(e[r]);
            atomicAdd(&s_partial, kl);
        }
    }

    __syncthreads();
    if (threadIdx.x == 0) {
        atomicAdd(&g_acc, (double)s_partial);
        __threadfence();
        unsigned int done = atomicAdd(&g_count, 1u);
        if (done == (unsigned int)(nblocks - 1)) {
            // all other blocks' g_acc additions are visible (fence + atomic order)
            double total = atomicAdd(&g_acc, 0.0);  // atomic read-modify for visibility
            out[0] = (float)(total / (double)n);
        }
    }
}

extern "C" void kernel_launch(void* const* d_in, const int* in_sizes, int n_in,
                              void* d_out, int out_size) {
    const float* scores = (const float*)d_in[0];
    const void*  labels = d_in[1];
    const int n = in_sizes[1];  // number of rows / labels

    prep<<<C, 32>>>((const int*)labels, n);
    int nblocks = (n + ROWS_PER_BLOCK - 1) / ROWS_PER_BLOCK;
    kl_main<<<nblocks, 256>>>(scores, labels, (float*)d_out, n, nblocks);
}

// round 6
// speedup vs baseline: 1.6528x; 1.1566x over previous
#include <cuda_runtime.h>
#include <cuda_bf16.h>

// KL(target || softmax(scores)), target = softmax(gaussian_pdf(classes; mu=label, std=1))
// kl_row = tlogt[L] - dot(T[L], s_row) + logsumexp(s_row);  out = mean over rows.
//
// Key trick this round: only the exp-sum `e` needs a per-row warp reduce (it
// feeds log). The dot product and the ent/log terms are accumulated per-lane /
// on lane 0 and reduced ONCE per warp at the end -> SHFL count cut by ~1/3.

#define C 100
#define ROWS_PER_WARP 4
#define WARPS_PER_BLOCK 8
#define ROWS_PER_BLOCK (ROWS_PER_WARP * WARPS_PER_BLOCK)  // 32

__device__ float         g_table[C * C];   // T[label][class]
__device__ float         g_ent[C];         // sum t*log t per label
__device__ double        g_acc;            // global accumulator
__device__ unsigned int  g_count;          // finished-block counter
__device__ int           g_is64;           // 1 if labels are int64, 0 if int32

// ---------------------------------------------------------------------------
// Kernel 1: build target table + entropy terms; block 0 also detects label
// dtype and zeroes accumulators. Grid: C blocks x 32 threads.
// ---------------------------------------------------------------------------
__global__ void prep(const int* __restrict__ labels_raw, int n) {
    const int L = blockIdx.x;
    const int lane = threadIdx.x;  // 0..31
    const float inv_norm = 0.39894228040143267794f;  // 1/sqrt(2*pi)

    if (blockIdx.x == 0) {
        // int64 little-endian labels => odd 32-bit words are all zero.
        int nz = 0;
        int limit = (n < 128) ? n : 128;
#pragma unroll
        for (int k = 0; k < 4; k++) {
            int i = lane + 32 * k;
            if (i < limit && labels_raw[2 * i + 1] != 0) nz = 1;
        }
        unsigned int ballot = __ballot_sync(0xffffffffu, nz);
        if (lane == 0) {
            g_is64 = (ballot == 0u) ? 1 : 0;
            g_acc = 0.0;
            g_count = 0u;
        }
    }

    float code[4];
    float esum = 0.f;
#pragma unroll
    for (int k = 0; k < 4; k++) {
        int c = lane + 32 * k;
        if (c < C) {
            float dd = (float)(c - L);
            code[k] = inv_norm * expf(-0.5f * dd * dd);
            esum += expf(code[k]);
        } else {
            code[k] = 0.f;
        }
    }
#pragma unroll
    for (int off = 16; off; off >>= 1)
        esum += __shfl_xor_sync(0xffffffffu, esum, off);

    float ls = logf(esum);
    float inv_s = 1.0f / esum;
    float tlt = 0.f;
#pragma unroll
    for (int k = 0; k < 4; k++) {
        int c = lane + 32 * k;
        if (c < C) {
            float t = expf(code[k]) * inv_s;
            g_table[L * C + c] = t;
            tlt += t * (code[k] - ls);  // t * log t
        }
    }
#pragma unroll
    for (int off = 16; off; off >>= 1)
        tlt += __shfl_xor_sync(0xffffffffu, tlt, off);

    if (lane == 0) g_ent[L] = tlt;
}

// ---------------------------------------------------------------------------
// Kernel 2: main streaming pass + fused finalize.
// One warp handles 4 rows; 8 float4 loads batched; only e gets a per-row
// reduce, everything else folds into one final per-warp reduce.
// ---------------------------------------------------------------------------
__global__ __launch_bounds__(256, 7) void kl_main(const float* __restrict__ scores,
                                                  const void* __restrict__ labels,
                                                  float* __restrict__ out,
                                                  int n, int nblocks) {
    const int warp = threadIdx.x >> 5;
    const int lane = threadIdx.x & 31;
    const int base_row = (blockIdx.x * WARPS_PER_BLOCK + warp) * ROWS_PER_WARP;

    __shared__ float s_partial;
    if (threadIdx.x == 0) s_partial = 0.f;
    __syncthreads();

    float v = 0.f;  // per-thread contribution to sum(kl)

    if (base_row < n) {
        // --- labels: lanes 0..3 each load one, then broadcast ---
        const int is64 = g_is64;
        int lab = 0;
        if (lane < ROWS_PER_WARP) {
            int r = base_row + lane;
            lab = is64 ? (int)((const long long*)labels)[r]
                       : ((const int*)labels)[r];
        }
        int L[ROWS_PER_WARP];
#pragma unroll
        for (int r = 0; r < ROWS_PER_WARP; r++)
            L[r] = __shfl_sync(0xffffffffu, lab, r);

        // --- batched loads: 8 independent float4 LDGs per lane ---
        float4 sv[ROWS_PER_WARP], tv[ROWS_PER_WARP];
        if (lane < 25) {
#pragma unroll
            for (int r = 0; r < ROWS_PER_WARP; r++)
                sv[r] = __ldcs((const float4*)(scores + (size_t)(base_row + r) * C) + lane);
#pragma unroll
            for (int r = 0; r < ROWS_PER_WARP; r++)
                tv[r] = ((const float4*)(g_table + L[r] * C))[lane];
        }

        // --- per-row exp-sum; dot accumulated per-lane (no per-row reduce) ---
        float e[ROWS_PER_WARP];
        float d_acc = 0.f;
#pragma unroll
        for (int r = 0; r < ROWS_PER_WARP; r++) {
            float ee = 0.f;
            if (lane < 25) {
                ee = __expf(sv[r].x) + __expf(sv[r].y) + __expf(sv[r].z) + __expf(sv[r].w);
                d_acc += tv[r].x * sv[r].x + tv[r].y * sv[r].y
                       + tv[r].z * sv[r].z + tv[r].w * sv[r].w;
            }
            e[r] = ee;
        }

        // --- warp reduce e only (needed inside log) ---
#pragma unroll
        for (int off = 16; off; off >>= 1) {
#pragma unroll
            for (int r = 0; r < ROWS_PER_WARP; r++)
                e[r] += __shfl_xor_sync(0xffffffffu, e[r], off);
        }

        v = -d_acc;
        if (lane == 0) {
#pragma unroll
            for (int r = 0; r < ROWS_PER_WARP; r++)
                v += g_ent[L[r]] + __logf(e[r]);
        }
    }

    // --- single final per-warp reduce of v ---
#pragma unroll
    for (int off = 16; off; off >>= 1)
        v += __shfl_xor_sync(0xffffffffu, v, off);

    if (lane == 0)
        atomicAdd(&s_partial, v);
    __syncthreads();

    if (threadIdx.x == 0) {
        atomicAdd(&g_acc, (double)s_partial);
        __threadfence();
        unsigned int done = atomicAdd(&g_count, 1u);
        if (done == (unsigned int)(nblocks - 1)) {
            double total = atomicAdd(&g_acc, 0.0);
            out[0] = (float)(total / (double)n);
        }
    }
}

extern "C" void kernel_launch(void* const* d_in, const int* in_sizes, int n_in,
                              void* d_out, int out_size) {
    const float* scores = (const float*)d_in[0];
    const void*  labels = d_in[1];
    const int n = in_sizes[1];  // number of rows / labels

    prep<<<C, 32>>>((const int*)labels, n);
    int nblocks = (n + ROWS_PER_BLOCK - 1) / ROWS_PER_BLOCK;
    kl_main<<<nblocks, 256>>>(scores, labels, (float*)d_out, n, nblocks);
}

// round 7
// speedup vs baseline: 2.1109x; 1.2772x over previous
#include <cuda_runtime.h>
#include <cuda_bf16.h>

// KL(target || softmax(scores)), target = softmax(gaussian_pdf(classes; mu=label, std=1))
// kl_row = ent[L] - dot(T[L], s_row) + logsumexp(s_row);  out = mean over rows.
//
// Factorization: T[L][c] = exp(code[c-L]) / S_L with code[k] = pdf(k).
//   dot(T[L], s) = invS_L * ( sum_c s_c  +  sum_{|k|<=8} w[k] * s_{L+k} ),
//   w[k] = expm1(code[k])   (|k|>8 terms are ~5e-15 -> machine-exact truncation).
// So no 100x100 table: a 17-float w vector (register-resident, static indices)
// + per-label (invS, ent) LUT + a 68B window reload per row (L1/L2 hit).
//
// Layout: 8 lanes per row -> 4 rows per warp in parallel; e-reduce = 3 shfl
// for all 4 rows; single final per-warp reduce after the row loop.

#define C 100
#define ROWS_PER_ITER 4     // one row per 8-lane group
#define ITERS 4             // rows per warp = 16
#define WARPS_PER_BLOCK 8
#define ROWS_PER_BLOCK (WARPS_PER_BLOCK * ROWS_PER_ITER * ITERS)  // 128

__device__ float2        g_lut[C];   // (invS_L, ent_L)
__device__ float         g_w[17];    // expm1(pdf(k)), k = i-8
__device__ double        g_acc;
__device__ unsigned int  g_count;
__device__ int           g_is64;

// ---------------------------------------------------------------------------
// Kernel 1: per-label (invS, ent) + w vector; block 0 detects label dtype and
// zeroes accumulators. Grid: C blocks x 32 threads.
// ---------------------------------------------------------------------------
__global__ void prep(const int* __restrict__ labels_raw, int n) {
    const int L = blockIdx.x;
    const int lane = threadIdx.x;  // 0..31
    const float inv_norm = 0.39894228040143267794f;  // 1/sqrt(2*pi)

    if (blockIdx.x == 0) {
        // int64 little-endian labels => odd 32-bit words all zero.
        int nz = 0;
        int limit = (n < 128) ? n : 128;
#pragma unroll
        for (int k = 0; k < 4; k++) {
            int i = lane + 32 * k;
            if (i < limit && labels_raw[2 * i + 1] != 0) nz = 1;
        }
        unsigned int ballot = __ballot_sync(0xffffffffu, nz);
        if (lane == 0) {
            g_is64 = (ballot == 0u) ? 1 : 0;
            g_acc = 0.0;
            g_count = 0u;
        }
        if (lane < 17) {
            float k = (float)(lane - 8);
            g_w[lane] = expm1f(inv_norm * expf(-0.5f * k * k));
        }
    }

    float code[4];
    float esum = 0.f;
#pragma unroll
    for (int k = 0; k < 4; k++) {
        int c = lane + 32 * k;
        if (c < C) {
            float dd = (float)(c - L);
            code[k] = inv_norm * expf(-0.5f * dd * dd);
            esum += expf(code[k]);
        } else {
            code[k] = 0.f;
        }
    }
#pragma unroll
    for (int off = 16; off; off >>= 1)
        esum += __shfl_xor_sync(0xffffffffu, esum, off);

    float ls = logf(esum);
    float inv_s = 1.0f / esum;
    float tlt = 0.f;
#pragma unroll
    for (int k = 0; k < 4; k++) {
        int c = lane + 32 * k;
        if (c < C) {
            float t = expf(code[k]) * inv_s;
            tlt += t * (code[k] - ls);  // t * log t
        }
    }
#pragma unroll
    for (int off = 16; off; off >>= 1)
        tlt += __shfl_xor_sync(0xffffffffu, tlt, off);

    if (lane == 0) g_lut[L] = make_float2(inv_s, tlt);
}

// ---------------------------------------------------------------------------
// Kernel 2: main streaming pass + fused finalize.
// ---------------------------------------------------------------------------
__global__ __launch_bounds__(256) void kl_main(const float* __restrict__ scores,
                                               const void* __restrict__ labels,
                                               float* __restrict__ out,
                                               int n, int nblocks) {
    const int warp = threadIdx.x >> 5;
    const int lane = threadIdx.x & 31;
    const int g    = lane >> 3;        // group (row within iter)
    const int j    = lane & 7;         // lane within group
    const int lead = lane & 24;        // group leader lane index

    __shared__ float s_partial;
    if (threadIdx.x == 0) s_partial = 0.f;
    __syncthreads();

    const int is64 = g_is64;
    // Static-index window weights: lane j owns window elems i=j, i=j+8,
    // and (j==0) i=16. Register-resident, loaded once.
    const float w0 = g_w[j];
    const float w1 = g_w[j + 8];
    const float w2 = (j == 0) ? g_w[16] : 0.f;

    float v = 0.f;  // per-thread contribution to sum(kl)
    const int warp_base = (blockIdx.x * WARPS_PER_BLOCK + warp) * (ROWS_PER_ITER * ITERS);

#pragma unroll
    for (int it = 0; it < ITERS; it++) {
        const int row = warp_base + it * ROWS_PER_ITER + g;
        const bool valid = (row < n);
        const float* srow = scores + (size_t)row * C;

        // --- label + lut: group leaders load, broadcast invS ---
        int lab = 0;
        if (j == 0 && valid)
            lab = is64 ? (int)((const long long*)labels)[row]
                       : ((const int*)labels)[row];
        const int L = __shfl_sync(0xffffffffu, lab, lead);
        float2 lut = make_float2(0.f, 0.f);
        if (j == 0 && valid) lut = g_lut[L];
        const float invS = __shfl_sync(0xffffffffu, lut.x, lead);

        // --- main streaming loads: 3 float4 per lane (+1 for j==0) ---
        float4 a = make_float4(0.f, 0.f, 0.f, 0.f), b = a, c4 = a, dd = a;
        if (valid) {
            const float4* sv = (const float4*)srow;
            a  = __ldcs(sv + j);
            b  = __ldcs(sv + j + 8);
            c4 = __ldcs(sv + j + 16);
            if (j == 0) dd = __ldcs(sv + 24);
        }

        // --- window reload (contiguous 68B around L; L1/L2 hit) ---
        const int c0 = L - 8 + j;   // in [L-8, L-1], always < C
        const int c1 = L + j;       // in [L, L+7],  always >= 0
        const int c2 = L + 8;
        float s0 = 0.f, s1 = 0.f, s2 = 0.f;
        if (valid) {
            if (c0 >= 0)           s0 = srow[c0];
            if (c1 < C)            s1 = srow[c1];
            if (j == 0 && c2 < C)  s2 = srow[c2];
        }

        // --- per-lane exp-sum and plain sum ---
        float e = 0.f, ps = 0.f;
        if (valid) {
            e  = __expf(a.x) + __expf(a.y) + __expf(a.z) + __expf(a.w)
               + __expf(b.x) + __expf(b.y) + __expf(b.z) + __expf(b.w)
               + __expf(c4.x) + __expf(c4.y) + __expf(c4.z) + __expf(c4.w);
            ps = a.x + a.y + a.z + a.w
               + b.x + b.y + b.z + b.w
               + c4.x + c4.y + c4.z + c4.w;
            if (j == 0) {
                e  += __expf(dd.x) + __expf(dd.y) + __expf(dd.z) + __expf(dd.w);
                ps += dd.x + dd.y + dd.z + dd.w;
            }
        }
        const float pc = w0 * s0 + w1 * s1 + w2 * s2;

        // --- group (8-lane) reduce of e: 3 shuffles cover all 4 rows ---
        e += __shfl_xor_sync(0xffffffffu, e, 1);
        e += __shfl_xor_sync(0xffffffffu, e, 2);
        e += __shfl_xor_sync(0xffffffffu, e, 4);

        if (valid) {
            v -= invS * (ps + pc);
            if (j == 0) v += lut.y + __logf(e);
        }
    }

    // --- single final per-warp reduce ---
#pragma unroll
    for (int off = 16; off; off >>= 1)
        v += __shfl_xor_sync(0xffffffffu, v, off);

    if (lane == 0)
        atomicAdd(&s_partial, v);
    __syncthreads();

    if (threadIdx.x == 0) {
        atomicAdd(&g_acc, (double)s_partial);
        __threadfence();
        unsigned int done = atomicAdd(&g_count, 1u);
        if (done == (unsigned int)(nblocks - 1)) {
            double total = atomicAdd(&g_acc, 0.0);
            out[0] = (float)(total / (double)n);
        }
    }
}

extern "C" void kernel_launch(void* const* d_in, const int* in_sizes, int n_in,
                              void* d_out, int out_size) {
    const float* scores = (const float*)d_in[0];
    const void*  labels = d_in[1];
    const int n = in_sizes[1];  // number of rows / labels

    prep<<<C, 32>>>((const int*)labels, n);
    int nblocks = (n + ROWS_PER_BLOCK - 1) / ROWS_PER_BLOCK;
    kl_main<<<nblocks, 256>>>(scores, labels, (float*)d_out, n, nblocks);
}

// round 8
// speedup vs baseline: 2.1602x; 1.0234x over previous
#include <cuda_runtime.h>
#include <cuda_bf16.h>

// KL(target || softmax(scores)), target = softmax(gaussian_pdf(classes; mu=label, std=1))
// kl_row = ent[L] - invS_L*(sum_c s_c + sum_{|k|<=8} w[k]*s_{L+k}) + logsumexp(s_row)
// w[k] = expm1(pdf(k)); |k|>8 terms ~5e-15 (machine-exact truncation).
//
// R8: labels+LUT hoisted out of the row loop (1 coalesced LDG each per warp,
// broadcast via shfl.idx) -> in-loop deps are only score/window LDGs.
// 8 iterations x 4 rows per warp for deep load pipelining.

#define C 100
#define ROWS_PER_ITER 4     // one row per 8-lane group
#define ITERS 8             // rows per warp = 32
#define WARPS_PER_BLOCK 8
#define ROWS_PER_BLOCK (WARPS_PER_BLOCK * ROWS_PER_ITER * ITERS)  // 256

__device__ float2        g_lut[C];   // (invS_L, ent_L)
__device__ float         g_w[17];    // expm1(pdf(k)), k = i-8
__device__ double        g_acc;
__device__ unsigned int  g_count;
__device__ int           g_is64;

// ---------------------------------------------------------------------------
// Kernel 1: per-label (invS, ent) + w vector; block 0 detects label dtype and
// zeroes accumulators. Grid: C blocks x 32 threads.
// ---------------------------------------------------------------------------
__global__ void prep(const int* __restrict__ labels_raw, int n) {
    const int L = blockIdx.x;
    const int lane = threadIdx.x;  // 0..31
    const float inv_norm = 0.39894228040143267794f;  // 1/sqrt(2*pi)

    if (blockIdx.x == 0) {
        int nz = 0;
        int limit = (n < 128) ? n : 128;
#pragma unroll
        for (int k = 0; k < 4; k++) {
            int i = lane + 32 * k;
            if (i < limit && labels_raw[2 * i + 1] != 0) nz = 1;
        }
        unsigned int ballot = __ballot_sync(0xffffffffu, nz);
        if (lane == 0) {
            g_is64 = (ballot == 0u) ? 1 : 0;
            g_acc = 0.0;
            g_count = 0u;
        }
        if (lane < 17) {
            float k = (float)(lane - 8);
            g_w[lane] = expm1f(inv_norm * expf(-0.5f * k * k));
        }
    }

    float code[4];
    float esum = 0.f;
#pragma unroll
    for (int k = 0; k < 4; k++) {
        int c = lane + 32 * k;
        if (c < C) {
            float dd = (float)(c - L);
            code[k] = inv_norm * expf(-0.5f * dd * dd);
            esum += expf(code[k]);
        } else {
            code[k] = 0.f;
        }
    }
#pragma unroll
    for (int off = 16; off; off >>= 1)
        esum += __shfl_xor_sync(0xffffffffu, esum, off);

    float ls = logf(esum);
    float inv_s = 1.0f / esum;
    float tlt = 0.f;
#pragma unroll
    for (int k = 0; k < 4; k++) {
        int c = lane + 32 * k;
        if (c < C) {
            float t = expf(code[k]) * inv_s;
            tlt += t * (code[k] - ls);  // t * log t
        }
    }
#pragma unroll
    for (int off = 16; off; off >>= 1)
        tlt += __shfl_xor_sync(0xffffffffu, tlt, off);

    if (lane == 0) g_lut[L] = make_float2(inv_s, tlt);
}

// ---------------------------------------------------------------------------
// Kernel 2: main streaming pass + fused finalize.
// ---------------------------------------------------------------------------
__global__ __launch_bounds__(256, 6) void kl_main(const float* __restrict__ scores,
                                                  const void* __restrict__ labels,
                                                  float* __restrict__ out,
                                                  int n, int nblocks) {
    const int warp = threadIdx.x >> 5;
    const int lane = threadIdx.x & 31;
    const int g    = lane >> 3;        // group (row within iter)
    const int j    = lane & 7;         // lane within group

    __shared__ float s_partial;
    if (threadIdx.x == 0) s_partial = 0.f;
    __syncthreads();

    // Window weights: lane j owns window elems i=j, i=j+8, (j==0) i=16.
    const float w0 = g_w[j];
    const float w1 = g_w[j + 8];
    const float w2 = (j == 0) ? g_w[16] : 0.f;

    const int warp_base = (blockIdx.x * WARPS_PER_BLOCK + warp) * (ROWS_PER_ITER * ITERS);

    // ---- hoisted label + LUT loads: lane i owns row warp_base+i ----
    const int my_row = warp_base + lane;
    int my_lab = 0;
    float2 my_lut = make_float2(0.f, 0.f);
    if (my_row < n) {
        my_lab = g_is64 ? (int)((const long long*)labels)[my_row]
                        : ((const int*)labels)[my_row];
        my_lut = g_lut[my_lab];
    }

    float v = 0.f;  // per-thread contribution to sum(kl)
    const bool all_valid = (warp_base + ROWS_PER_ITER * ITERS) <= n;

    if (all_valid) {
#pragma unroll
        for (int it = 0; it < ITERS; it++) {
            const int src = it * ROWS_PER_ITER + g;      // uniform within group
            const int L     = __shfl_sync(0xffffffffu, my_lab,   src);
            const float invS= __shfl_sync(0xffffffffu, my_lut.x, src);
            const float ent = __shfl_sync(0xffffffffu, my_lut.y, src);

            const int row = warp_base + src;
            const float* srow = scores + (size_t)row * C;
            const float4* sv = (const float4*)srow;

            // streaming loads (3 float4 per lane, +1 on j==0)
            float4 a  = __ldcs(sv + j);
            float4 b  = __ldcs(sv + j + 8);
            float4 c4 = __ldcs(sv + j + 16);
            float4 dd = make_float4(0.f, 0.f, 0.f, 0.f);
            if (j == 0) dd = __ldcs(sv + 24);

            // window reload around L (L1/L2 hit); L known with no mem dep
            const int c0 = L - 8 + j;
            const int c1 = L + j;
            float s0 = (c0 >= 0) ? srow[c0] : 0.f;
            float s1 = (c1 < C)  ? srow[c1] : 0.f;
            float s2 = (j == 0 && L + 8 < C) ? srow[L + 8] : 0.f;

            float e  = __expf(a.x) + __expf(a.y) + __expf(a.z) + __expf(a.w)
                     + __expf(b.x) + __expf(b.y) + __expf(b.z) + __expf(b.w)
                     + __expf(c4.x) + __expf(c4.y) + __expf(c4.z) + __expf(c4.w);
            float ps = a.x + a.y + a.z + a.w
                     + b.x + b.y + b.z + b.w
                     + c4.x + c4.y + c4.z + c4.w;
            if (j == 0) {
                e  += __expf(dd.x) + __expf(dd.y) + __expf(dd.z) + __expf(dd.w);
                ps += dd.x + dd.y + dd.z + dd.w;
            }
            const float pc = w0 * s0 + w1 * s1 + w2 * s2;

            // 8-lane group reduce of e (covers all 4 rows at once)
            e += __shfl_xor_sync(0xffffffffu, e, 1);
            e += __shfl_xor_sync(0xffffffffu, e, 2);
            e += __shfl_xor_sync(0xffffffffu, e, 4);

            v -= invS * (ps + pc);
            if (j == 0) v += ent + __logf(e);
        }
    } else {
        for (int it = 0; it < ITERS; it++) {
            const int src = it * ROWS_PER_ITER + g;
            const int row = warp_base + src;
            const bool valid = (row < n);
            const int L     = __shfl_sync(0xffffffffu, my_lab,   src);
            const float invS= __shfl_sync(0xffffffffu, my_lut.x, src);
            const float ent = __shfl_sync(0xffffffffu, my_lut.y, src);
            const float* srow = scores + (size_t)row * C;
            const float4* sv = (const float4*)srow;

            float4 a = make_float4(0.f,0.f,0.f,0.f), b = a, c4 = a, dd = a;
            float s0 = 0.f, s1 = 0.f, s2 = 0.f;
            if (valid) {
                a  = __ldcs(sv + j);
                b  = __ldcs(sv + j + 8);
                c4 = __ldcs(sv + j + 16);
                if (j == 0) dd = __ldcs(sv + 24);
                const int c0 = L - 8 + j;
                const int c1 = L + j;
                if (c0 >= 0) s0 = srow[c0];
                if (c1 < C)  s1 = srow[c1];
                if (j == 0 && L + 8 < C) s2 = srow[L + 8];
            }
            float e = 0.f, ps = 0.f;
            if (valid) {
                e  = __expf(a.x) + __expf(a.y) + __expf(a.z) + __expf(a.w)
                   + __expf(b.x) + __expf(b.y) + __expf(b.z) + __expf(b.w)
                   + __expf(c4.x) + __expf(c4.y) + __expf(c4.z) + __expf(c4.w);
                ps = a.x + a.y + a.z + a.w + b.x + b.y + b.z + b.w
                   + c4.x + c4.y + c4.z + c4.w;
                if (j == 0) {
                    e  += __expf(dd.x) + __expf(dd.y) + __expf(dd.z) + __expf(dd.w);
                    ps += dd.x + dd.y + dd.z + dd.w;
                }
            }
            const float pc = w0 * s0 + w1 * s1 + w2 * s2;
            e += __shfl_xor_sync(0xffffffffu, e, 1);
            e += __shfl_xor_sync(0xffffffffu, e, 2);
            e += __shfl_xor_sync(0xffffffffu, e, 4);
            if (valid) {
                v -= invS * (ps + pc);
                if (j == 0) v += ent + __logf(e);
            }
        }
    }

    // single final per-warp reduce
#pragma unroll
    for (int off = 16; off; off >>= 1)
        v += __shfl_xor_sync(0xffffffffu, v, off);

    if (lane == 0)
        atomicAdd(&s_partial, v);
    __syncthreads();

    if (threadIdx.x == 0) {
        atomicAdd(&g_acc, (double)s_partial);
        __threadfence();
        unsigned int done = atomicAdd(&g_count, 1u);
        if (done == (unsigned int)(nblocks - 1)) {
            double total = atomicAdd(&g_acc, 0.0);
            out[0] = (float)(total / (double)n);
        }
    }
}

extern "C" void kernel_launch(void* const* d_in, const int* in_sizes, int n_in,
                              void* d_out, int out_size) {
    const float* scores = (const float*)d_in[0];
    const void*  labels = d_in[1];
    const int n = in_sizes[1];  // number of rows / labels

    prep<<<C, 32>>>((const int*)labels, n);
    int nblocks = (n + ROWS_PER_BLOCK - 1) / ROWS_PER_BLOCK;
    kl_main<<<nblocks, 256>>>(scores, labels, (float*)d_out, n, nblocks);
}

// round 11
// speedup vs baseline: 2.2713x; 1.0515x over previous
#include <cuda_runtime.h>
#include <cuda_bf16.h>

// KL(target || softmax(scores)), target = softmax(gaussian_pdf(classes; mu=label, std=1))
// kl_row = ent[L] - invS_L*(sum_c s_c + sum_{|k|<=8} w[k]*s_{L+k}) + logsumexp(s_row)
// w[k] = expm1(pdf(k)); |k|>8 terms ~5e-15 (machine-exact truncation).
//
// R9 (resubmit after infra failure): persistent single-wave grid (888 = 148
// SMs x 6 blocks) + warp-stride loop over 4-row chunks (65536 chunks) -> no
// wave quantization, ~3% tail. Labels software-pipelined (next chunk's labels
// prefetched each iteration).

#define C 100
#define GRID_BLOCKS 888
#define WARPS_PER_BLOCK 8

__device__ float2        g_lut[C];   // (invS_L, ent_L)
__device__ float         g_w[17];    // expm1(pdf(k)), k = i-8
__device__ double        g_acc;
__device__ unsigned int  g_count;
__device__ int           g_is64;

// ---------------------------------------------------------------------------
// Kernel 1: per-label (invS, ent) + w vector; block 0 detects label dtype and
// zeroes accumulators. Grid: C blocks x 32 threads.
// ---------------------------------------------------------------------------
__global__ void prep(const int* __restrict__ labels_raw, int n) {
    const int L = blockIdx.x;
    const int lane = threadIdx.x;  // 0..31
    const float inv_norm = 0.39894228040143267794f;  // 1/sqrt(2*pi)

    if (blockIdx.x == 0) {
        int nz = 0;
        int limit = (n < 128) ? n : 128;
#pragma unroll
        for (int k = 0; k < 4; k++) {
            int i = lane + 32 * k;
            if (i < limit && labels_raw[2 * i + 1] != 0) nz = 1;
        }
        unsigned int ballot = __ballot_sync(0xffffffffu, nz);
        if (lane == 0) {
            g_is64 = (ballot == 0u) ? 1 : 0;
            g_acc = 0.0;
            g_count = 0u;
        }
        if (lane < 17) {
            float k = (float)(lane - 8);
            g_w[lane] = expm1f(inv_norm * expf(-0.5f * k * k));
        }
    }

    float code[4];
    float esum = 0.f;
#pragma unroll
    for (int k = 0; k < 4; k++) {
        int c = lane + 32 * k;
        if (c < C) {
            float dd = (float)(c - L);
            code[k] = inv_norm * expf(-0.5f * dd * dd);
            esum += expf(code[k]);
        } else {
            code[k] = 0.f;
        }
    }
#pragma unroll
    for (int off = 16; off; off >>= 1)
        esum += __shfl_xor_sync(0xffffffffu, esum, off);

    float ls = logf(esum);
    float inv_s = 1.0f / esum;
    float tlt = 0.f;
#pragma unroll
    for (int k = 0; k < 4; k++) {
        int c = lane + 32 * k;
        if (c < C) {
            float t = expf(code[k]) * inv_s;
            tlt += t * (code[k] - ls);  // t * log t
        }
    }
#pragma unroll
    for (int off = 16; off; off >>= 1)
        tlt += __shfl_xor_sync(0xffffffffu, tlt, off);

    if (lane == 0) g_lut[L] = make_float2(inv_s, tlt);
}

// ---------------------------------------------------------------------------
// Kernel 2: persistent streaming pass + fused finalize.
// Each warp strides over 4-row chunks; 8 lanes per row.
// ---------------------------------------------------------------------------
__global__ __launch_bounds__(256, 6) void kl_main(const float* __restrict__ scores,
                                                  const void* __restrict__ labels,
                                                  float* __restrict__ out,
                                                  int n, int nblocks) {
    const int warp = threadIdx.x >> 5;
    const int lane = threadIdx.x & 31;
    const int g    = lane >> 3;        // group (row within chunk)
    const int j    = lane & 7;         // lane within group

    __shared__ float s_partial;
    if (threadIdx.x == 0) s_partial = 0.f;
    __syncthreads();

    const int is64 = g_is64;
    // Window weights: lane j owns window elems i=j, i=j+8, (j==0) i=16.
    const float w0 = g_w[j];
    const float w1 = g_w[j + 8];
    const float w2 = (j == 0) ? g_w[16] : 0.f;

    const int total_warps = gridDim.x * WARPS_PER_BLOCK;
    const int nchunks = (n + 3) >> 2;   // 4-row chunks

    float v = 0.f;  // per-thread contribution to sum(kl)

    int chunk = blockIdx.x * WARPS_PER_BLOCK + warp;

    // --- prefetch labels for first chunk (lanes 0..3) ---
    int lab = 0;
    if (chunk < nchunks && lane < 4) {
        int r = chunk * 4 + lane;
        if (r >= n) r = n - 1;
        lab = is64 ? (int)((const long long*)labels)[r]
                   : ((const int*)labels)[r];
    }

    while (chunk < nchunks) {
        const int next = chunk + total_warps;

        // --- prefetch next chunk's labels early (independent of this chunk) ---
        int nlab = 0;
        if (next < nchunks && lane < 4) {
            int r = next * 4 + lane;
            if (r >= n) r = n - 1;
            nlab = is64 ? (int)((const long long*)labels)[r]
                        : ((const int*)labels)[r];
        }

        // --- LUT for current labels (L1-hot, 800B table) ---
        float2 lut = make_float2(0.f, 0.f);
        if (lane < 4) lut = g_lut[lab];

        const int   L    = __shfl_sync(0xffffffffu, lab,   g);
        const float invS = __shfl_sync(0xffffffffu, lut.x, g);
        const float ent  = __shfl_sync(0xffffffffu, lut.y, g);

        const int row = chunk * 4 + g;
        const bool valid = (row < n);
        const float* srow = scores + (size_t)row * C;
        const float4* sv = (const float4*)srow;

        // --- streaming loads: 3 float4 per lane (+1 on j==0) ---
        float4 a = make_float4(0.f, 0.f, 0.f, 0.f), b = a, c4 = a, dd = a;
        float s0 = 0.f, s1 = 0.f, s2 = 0.f;
        if (valid) {
            a  = __ldcs(sv + j);
            b  = __ldcs(sv + j + 8);
            c4 = __ldcs(sv + j + 16);
            if (j == 0) dd = __ldcs(sv + 24);
            // window reload around L (L1/L2 hit)
            const int c0 = L - 8 + j;
            const int c1 = L + j;
            if (c0 >= 0) s0 = srow[c0];
            if (c1 < C)  s1 = srow[c1];
            if (j == 0 && L + 8 < C) s2 = srow[L + 8];
        }

        float e = 0.f, ps = 0.f;
        if (valid) {
            e  = __expf(a.x) + __expf(a.y) + __expf(a.z) + __expf(a.w)
               + __expf(b.x) + __expf(b.y) + __expf(b.z) + __expf(b.w)
               + __expf(c4.x) + __expf(c4.y) + __expf(c4.z) + __expf(c4.w);
            ps = a.x + a.y + a.z + a.w
               + b.x + b.y + b.z + b.w
               + c4.x + c4.y + c4.z + c4.w;
            if (j == 0) {
                e  += __expf(dd.x) + __expf(dd.y) + __expf(dd.z) + __expf(dd.w);
                ps += dd.x + dd.y + dd.z + dd.w;
            }
        }
        const float pc = w0 * s0 + w1 * s1 + w2 * s2;

        // --- 8-lane group reduce of e (covers all 4 rows at once) ---
        e += __shfl_xor_sync(0xffffffffu, e, 1);
        e += __shfl_xor_sync(0xffffffffu, e, 2);
        e += __shfl_xor_sync(0xffffffffu, e, 4);

        if (valid) {
            v -= invS * (ps + pc);
            if (j == 0) v += ent + __logf(e);
        }

        lab = nlab;
        chunk = next;
    }

    // --- single final per-warp reduce ---
#pragma unroll
    for (int off = 16; off; off >>= 1)
        v += __shfl_xor_sync(0xffffffffu, v, off);

    if (lane == 0)
        atomicAdd(&s_partial, v);
    __syncthreads();

    if (threadIdx.x == 0) {
        atomicAdd(&g_acc, (double)s_partial);
        __threadfence();
        unsigned int done = atomicAdd(&g_count, 1u);
        if (done == (unsigned int)(nblocks - 1)) {
            double total = atomicAdd(&g_acc, 0.0);
            out[0] = (float)(total / (double)n);
        }
    }
}

extern "C" void kernel_launch(void* const* d_in, const int* in_sizes, int n_in,
                              void* d_out, int out_size) {
    const float* scores = (const float*)d_in[0];
    const void*  labels = d_in[1];
    const int n = in_sizes[1];  // number of rows / labels

    prep<<<C, 32>>>((const int*)labels, n);
    kl_main<<<GRID_BLOCKS, 256>>>(scores, labels, (float*)d_out, n, GRID_BLOCKS);
}